// round 1
// baseline (speedup 1.0000x reference)
#include <cuda_runtime.h>
#include <cuda_bf16.h>
#include <math.h>

#define NN 50000
#define NE 800000
#define DD 128
#define NG 3

// ---------------- scratch (static device memory; no allocs allowed) ----------
__device__ int   d_deg[NG][NN];
__device__ int   d_start[NG][NN + 1];
__device__ int   d_cursor[NG][NN];
__device__ int   d_srcs[NG][NE];
__device__ float d_dinv[NG][NN];
__device__ float d_z[NG][NN * DD];     // aggregated features
__device__ float d_gsum[NG][DD];       // pooled graph signatures

// ---------------- kernels ----------------------------------------------------

__global__ void zero_kernel() {
    int i = blockIdx.x * blockDim.x + threadIdx.x;
    int stride = gridDim.x * blockDim.x;
    for (int j = i; j < NG * NN; j += stride) ((int*)d_deg)[j] = 0;
    for (int j = i; j < NG * DD; j += stride) ((float*)d_gsum)[j] = 0.0f;
}

__global__ void hist_kernel(const int* __restrict__ e1,
                            const int* __restrict__ e2,
                            const int* __restrict__ e3) {
    int g = blockIdx.y;
    const int* ei = (g == 0) ? e1 : ((g == 1) ? e2 : e3);
    const int* dst = ei + NE;
    int stride = gridDim.x * blockDim.x;
    for (int i = blockIdx.x * blockDim.x + threadIdx.x; i < NE; i += stride)
        atomicAdd(&d_deg[g][dst[i]], 1);
}

// one block per graph: exclusive scan of degrees -> CSR offsets, cursors, dinv
__global__ void scan_kernel() {
    int g = blockIdx.x;
    __shared__ int sh[1024];
    __shared__ int carry;
    int t = threadIdx.x;
    if (t == 0) carry = 0;
    __syncthreads();
    for (int base = 0; base < NN; base += 1024) {
        int idx = base + t;
        int v = (idx < NN) ? d_deg[g][idx] : 0;
        int x = v;
        #pragma unroll
        for (int off = 1; off < 1024; off <<= 1) {
            sh[t] = x;
            __syncthreads();
            int y = (t >= off) ? sh[t - off] : 0;
            __syncthreads();
            x += y;
        }
        int incl = x + carry;
        if (idx < NN) {
            int excl = incl - v;
            d_start[g][idx]  = excl;
            d_cursor[g][idx] = excl;
            d_dinv[g][idx]   = rsqrtf((float)(v + 1));   // +1 self loop
        }
        __syncthreads();
        if (t == 1023) carry = incl;
        __syncthreads();
    }
    if (t == 0) d_start[g][NN] = carry;
}

__global__ void fill_kernel(const int* __restrict__ e1,
                            const int* __restrict__ e2,
                            const int* __restrict__ e3) {
    int g = blockIdx.y;
    const int* ei = (g == 0) ? e1 : ((g == 1) ? e2 : e3);
    const int* src = ei;
    const int* dst = ei + NE;
    int stride = gridDim.x * blockDim.x;
    for (int i = blockIdx.x * blockDim.x + threadIdx.x; i < NE; i += stride) {
        int pos = atomicAdd(&d_cursor[g][dst[i]], 1);
        d_srcs[g][pos] = src[i];
    }
}

// one warp per destination node: z[dst] = dinv[dst]*sum(dinv[src]*x[src]) + dinv[dst]^2*x[dst]
__global__ void gather_kernel(const float* __restrict__ x1,
                              const float* __restrict__ x2,
                              const float* __restrict__ x3) {
    int g = blockIdx.y;
    const float4* x4 = (const float4*)((g == 0) ? x1 : ((g == 1) ? x2 : x3));
    int warp = (blockIdx.x * blockDim.x + threadIdx.x) >> 5;
    int lane = threadIdx.x & 31;
    if (warp >= NN) return;
    int n = warp;
    int s = d_start[g][n];
    int e = d_start[g][n + 1];
    const int*   srcs = d_srcs[g];
    const float* dinv = d_dinv[g];
    float4 acc = make_float4(0.f, 0.f, 0.f, 0.f);
    int i = s;
    for (; i + 4 <= e; i += 4) {
        int s0 = srcs[i], s1 = srcs[i + 1], s2 = srcs[i + 2], s3 = srcs[i + 3];
        float w0 = dinv[s0], w1 = dinv[s1], w2 = dinv[s2], w3 = dinv[s3];
        float4 a0 = x4[s0 * 32 + lane];
        float4 a1 = x4[s1 * 32 + lane];
        float4 a2 = x4[s2 * 32 + lane];
        float4 a3 = x4[s3 * 32 + lane];
        acc.x += w0 * a0.x + w1 * a1.x + w2 * a2.x + w3 * a3.x;
        acc.y += w0 * a0.y + w1 * a1.y + w2 * a2.y + w3 * a3.y;
        acc.z += w0 * a0.z + w1 * a1.z + w2 * a2.z + w3 * a3.z;
        acc.w += w0 * a0.w + w1 * a1.w + w2 * a2.w + w3 * a3.w;
    }
    for (; i < e; i++) {
        int s0 = srcs[i];
        float w0 = dinv[s0];
        float4 a0 = x4[s0 * 32 + lane];
        acc.x += w0 * a0.x; acc.y += w0 * a0.y;
        acc.z += w0 * a0.z; acc.w += w0 * a0.w;
    }
    float di = dinv[n];
    float c2 = di * di;
    float4 self = x4[n * 32 + lane];
    float4 r;
    r.x = di * acc.x + c2 * self.x;
    r.y = di * acc.y + c2 * self.y;
    r.z = di * acc.z + c2 * self.z;
    r.w = di * acc.w + c2 * self.w;
    ((float4*)d_z[g])[n * 32 + lane] = r;
}

// fused: relu(z @ W + b) column-summed into d_gsum. Tile: 64 rows x 128 cols.
__global__ void gemm_kernel(const float* __restrict__ W1, const float* __restrict__ b1,
                            const float* __restrict__ W2, const float* __restrict__ b2,
                            const float* __restrict__ W3, const float* __restrict__ b3) {
    extern __shared__ float sm[];
    float* Ws = sm;            // 128*128 floats (W[k][j])
    float* zs = sm + 16384;    // 128*64 floats, transposed: zs[k*64 + r]
    int g = blockIdx.y;
    const float* W = (g == 0) ? W1 : ((g == 1) ? W2 : W3);
    const float* b = (g == 0) ? b1 : ((g == 1) ? b2 : b3);
    int t = threadIdx.x;       // 256 threads
    int row0 = blockIdx.x * 64;

    const float4* W4 = (const float4*)W;
    float4* Ws4 = (float4*)Ws;
    #pragma unroll
    for (int i = t; i < 4096; i += 256) Ws4[i] = W4[i];

    const float4* z4 = (const float4*)d_z[g];
    for (int idx = t; idx < 64 * 32; idx += 256) {
        int r = idx >> 5, c4 = idx & 31;
        int row = row0 + r;
        float4 v = (row < NN) ? z4[row * 32 + c4] : make_float4(0.f, 0.f, 0.f, 0.f);
        int k = c4 * 4;
        zs[(k + 0) * 64 + r] = v.x;
        zs[(k + 1) * 64 + r] = v.y;
        zs[(k + 2) * 64 + r] = v.z;
        zs[(k + 3) * 64 + r] = v.w;
    }
    __syncthreads();

    int tx = t & 31;   // 4 output columns: tx*4 .. tx*4+3
    int ty = t >> 5;   // 8 output rows:    ty*8 .. ty*8+7
    float acc[8][4];
    #pragma unroll
    for (int r = 0; r < 8; r++)
        #pragma unroll
        for (int c = 0; c < 4; c++) acc[r][c] = 0.f;

    #pragma unroll 8
    for (int k = 0; k < 128; k++) {
        const float4 wv = *(const float4*)(Ws + k * 128 + tx * 4);
        const float4 za = *(const float4*)(zs + k * 64 + ty * 8);
        const float4 zb = *(const float4*)(zs + k * 64 + ty * 8 + 4);
        float zr[8] = {za.x, za.y, za.z, za.w, zb.x, zb.y, zb.z, zb.w};
        #pragma unroll
        for (int r = 0; r < 8; r++) {
            acc[r][0] = fmaf(zr[r], wv.x, acc[r][0]);
            acc[r][1] = fmaf(zr[r], wv.y, acc[r][1]);
            acc[r][2] = fmaf(zr[r], wv.z, acc[r][2]);
            acc[r][3] = fmaf(zr[r], wv.w, acc[r][3]);
        }
    }

    // epilogue: +b, relu, per-thread column sums over its 8 rows
    float bb[4];
    #pragma unroll
    for (int c = 0; c < 4; c++) bb[c] = b[tx * 4 + c];
    float colsum[4] = {0.f, 0.f, 0.f, 0.f};
    #pragma unroll
    for (int r = 0; r < 8; r++) {
        int row = row0 + ty * 8 + r;
        if (row < NN) {
            #pragma unroll
            for (int c = 0; c < 4; c++) {
                float v = acc[r][c] + bb[c];
                colsum[c] += fmaxf(v, 0.f);
            }
        }
    }
    __syncthreads();
    float* red = zs;  // reuse: 8 x 128 floats
    #pragma unroll
    for (int c = 0; c < 4; c++) red[ty * 128 + tx * 4 + c] = colsum[c];
    __syncthreads();
    if (ty == 0) {
        #pragma unroll
        for (int c = 0; c < 4; c++) {
            float s = 0.f;
            #pragma unroll
            for (int yy = 0; yy < 8; yy++) s += red[yy * 128 + tx * 4 + c];
            atomicAdd(&d_gsum[g][tx * 4 + c], s);
        }
    }
}

// tiny attention + FiLM head; single block of 128 threads
__global__ void finalize_kernel(const float* __restrict__ a1w, const float* __restrict__ a1b,
                                const float* __restrict__ a2w, const float* __restrict__ a2b,
                                const float* __restrict__ a3w, const float* __restrict__ a3b,
                                const float* __restrict__ f1w, const float* __restrict__ f1b,
                                const float* __restrict__ f2w, const float* __restrict__ f2b,
                                float* __restrict__ out) {
    __shared__ float xin[3 * DD];
    __shared__ float h1[DD];
    __shared__ float h2[DD];
    __shared__ float aw[4];
    __shared__ float xa[DD];
    int t = threadIdx.x;
    xin[t]            = d_gsum[0][t];
    xin[DD + t]       = d_gsum[1][t];
    xin[2 * DD + t]   = d_gsum[2][t];
    __syncthreads();
    // h1 = relu(xin @ a1w.T + a1b); a1w: (128, 384) row-major
    {
        float s = a1b[t];
        for (int j = 0; j < 3 * DD; j++) s += xin[j] * a1w[t * (3 * DD) + j];
        h1[t] = fmaxf(s, 0.f);
    }
    __syncthreads();
    // h2 = h1 @ a2w.T + a2b (no relu stored)
    {
        float s = a2b[t];
        for (int j = 0; j < DD; j++) s += h1[j] * a2w[t * DD + j];
        h2[t] = s;
    }
    __syncthreads();
    // logits = relu(h2) @ a3w.T + a3b; a3w: (3, 128)
    if (t < 3) {
        float s = a3b[t];
        for (int j = 0; j < DD; j++) s += fmaxf(h2[j], 0.f) * a3w[t * DD + j];
        aw[t] = s;
    }
    __syncthreads();
    if (t == 0) {
        float m = fmaxf(aw[0], fmaxf(aw[1], aw[2]));
        float e0 = expf(aw[0] - m), e1 = expf(aw[1] - m), e2 = expf(aw[2] - m);
        float S = e0 + e1 + e2;
        aw[0] = e0 / S; aw[1] = e1 / S; aw[2] = e2 / S;
    }
    __syncthreads();
    xa[t] = aw[0] * xin[t] + aw[1] * xin[DD + t] + aw[2] * xin[2 * DD + t];
    __syncthreads();
    float sg = f1b[t], sb = f2b[t];
    for (int j = 0; j < DD; j++) {
        float v = xa[j];
        sg += v * f1w[t * DD + j];
        sb += v * f2w[t * DD + j];
    }
    out[t]      = tanhf(sg);
    out[DD + t] = tanhf(sb);
}

// ---------------- launch ------------------------------------------------------
extern "C" void kernel_launch(void* const* d_in, const int* in_sizes, int n_in,
                              void* d_out, int out_size) {
    const float* x1 = (const float*)d_in[0];
    const float* x2 = (const float*)d_in[1];
    const float* x3 = (const float*)d_in[2];
    const int* e1 = (const int*)d_in[3];
    const int* e2 = (const int*)d_in[4];
    const int* e3 = (const int*)d_in[5];
    const float* W1 = (const float*)d_in[6];  const float* b1 = (const float*)d_in[7];
    const float* W2 = (const float*)d_in[8];  const float* b2 = (const float*)d_in[9];
    const float* W3 = (const float*)d_in[10]; const float* b3 = (const float*)d_in[11];
    const float* a1w = (const float*)d_in[12]; const float* a1b = (const float*)d_in[13];
    const float* a2w = (const float*)d_in[14]; const float* a2b = (const float*)d_in[15];
    const float* a3w = (const float*)d_in[16]; const float* a3b = (const float*)d_in[17];
    const float* f1w = (const float*)d_in[18]; const float* f1b = (const float*)d_in[19];
    const float* f2w = (const float*)d_in[20]; const float* f2b = (const float*)d_in[21];
    float* out = (float*)d_out;

    static bool smem_set = false;
    if (!smem_set) {
        cudaFuncSetAttribute(gemm_kernel, cudaFuncAttributeMaxDynamicSharedMemorySize, 98304);
        smem_set = true;
    }

    zero_kernel<<<256, 256>>>();
    hist_kernel<<<dim3(512, NG), 256>>>(e1, e2, e3);
    scan_kernel<<<NG, 1024>>>();
    fill_kernel<<<dim3(512, NG), 256>>>(e1, e2, e3);
    gather_kernel<<<dim3((NN + 7) / 8, NG), 256>>>(x1, x2, x3);
    gemm_kernel<<<dim3((NN + 63) / 64, NG), 256, 98304>>>(W1, b1, W2, b2, W3, b3);
    finalize_kernel<<<1, DD>>>(a1w, a1b, a2w, a2b, a3w, a3b, f1w, f1b, f2w, f2b, out);
}